// round 12
// baseline (speedup 1.0000x reference)
#include <cuda_runtime.h>
#include <math.h>
#include <stdint.h>

#define BB   32
#define TT   128
#define G3   1536
#define NCTA 128
#define NTHR 192
#define HSP  33
#define USP  516

__device__ float g_e   [BB*TT*512];
__device__ int   g_mask[BB*TT];
__device__ float g_xp0 [BB*TT*G3];
__device__ float g_xp1 [BB*TT*G3];
__device__ float g_hcat[BB*TT*1024];
__device__ float g_y   [BB*TT*512];
__device__ float g_h   [2*2*BB*512];
__device__ unsigned int g_bar[4*132];
__device__ int   g_is64;

__device__ __forceinline__ float sigf(float x){ return 1.f/(1.f + __expf(-x)); }

__global__ void prep_kernel(const int* xw){
    __shared__ int s_ok;
    if (threadIdx.x == 0) s_ok = 1;
    __syncthreads();
    int bad = 0;
    for (int i = threadIdx.x; i < 2040; i += blockDim.x)
        if (xw[2*i + 1] != 0) bad = 1;
    if (bad) atomicExch(&s_ok, 0);
    __syncthreads();
    if (threadIdx.x == 0) g_is64 = s_ok;
    for (int i = threadIdx.x; i < 4*132; i += blockDim.x) g_bar[i] = 0u;
}

__global__ void embed_kernel(const int* xw, const float* E){
    int i = blockIdx.x;
    int tok = g_is64 ? xw[2*i] : xw[i];
    if (threadIdx.x == 0) g_mask[i] = (tok != 0);
    const float4* src = (const float4*)(E + (size_t)tok * 512);
    float4* dst = (float4*)(g_e + (size_t)i * 512);
    dst[threadIdx.x] = src[threadIdx.x];
}

__global__ __launch_bounds__(256)
void gemm_kernel(const float* A, int lda, int K,
                 const float* Bm, const float* bias, float* C){
    __shared__ float As[8*128];
    __shared__ float Bs[8*128];
    int tid = threadIdx.x;
    int m0 = blockIdx.y * 128, n0 = blockIdx.x * 128;
    int tx = tid & 15, ty = tid >> 4;
    int arow = tid >> 1, akq = (tid & 1) * 4;
    int bkr  = tid >> 5, bnc = (tid & 31) * 4;
    const float* Aptr = A + (size_t)(m0 + arow) * lda + akq;
    const float* Bptr = Bm + (size_t)bkr * G3 + n0 + bnc;

    float acc[8][8];
    #pragma unroll
    for (int i = 0; i < 8; i++)
        #pragma unroll
        for (int j = 0; j < 8; j++) acc[i][j] = 0.f;

    int KT = K >> 3;
    float4 ra = *(const float4*)(Aptr);
    float4 rb = *(const float4*)(Bptr);
    for (int kt = 0; kt < KT; kt++){
        As[(akq+0)*128 + arow] = ra.x;
        As[(akq+1)*128 + arow] = ra.y;
        As[(akq+2)*128 + arow] = ra.z;
        As[(akq+3)*128 + arow] = ra.w;
        *(float4*)(Bs + bkr*128 + bnc) = rb;
        __syncthreads();
        if (kt + 1 < KT){
            ra = *(const float4*)(Aptr + (kt+1)*8);
            rb = *(const float4*)(Bptr + (size_t)(kt+1)*8*G3);
        }
        #pragma unroll
        for (int kk = 0; kk < 8; kk++){
            float a[8], b[8];
            *(float4*)(a)   = *(const float4*)(As + kk*128 + ty*8);
            *(float4*)(a+4) = *(const float4*)(As + kk*128 + ty*8 + 4);
            *(float4*)(b)   = *(const float4*)(Bs + kk*128 + tx*8);
            *(float4*)(b+4) = *(const float4*)(Bs + kk*128 + tx*8 + 4);
            #pragma unroll
            for (int i = 0; i < 8; i++)
                #pragma unroll
                for (int j = 0; j < 8; j++) acc[i][j] += a[i]*b[j];
        }
        __syncthreads();
    }
    float bb[8];
    #pragma unroll
    for (int j = 0; j < 8; j++) bb[j] = bias[n0 + tx*8 + j];
    #pragma unroll
    for (int i = 0; i < 8; i++){
        float* crow = C + (size_t)(m0 + ty*8 + i)*G3 + n0 + tx*8;
        float4 o0, o1;
        o0.x = acc[i][0]+bb[0]; o0.y = acc[i][1]+bb[1]; o0.z = acc[i][2]+bb[2]; o0.w = acc[i][3]+bb[3];
        o1.x = acc[i][4]+bb[4]; o1.y = acc[i][5]+bb[5]; o1.z = acc[i][6]+bb[6]; o1.w = acc[i][7]+bb[7];
        *(float4*)(crow)     = o0;
        *(float4*)(crow + 4) = o1;
    }
}

template<int NDIR>
__global__ __launch_bounds__(NTHR)
void scan_kernel(const float* xpA, const float* UA, const float* brA, float* yA, int revA, int yoffA,
                 const float* xpB, const float* UB, const float* brB, float* yB, int revB, int yoffB,
                 int ystride, unsigned int* bar, int write_hT)
{
    extern __shared__ float sm[];
    float* Us   = sm;
    float* hs   = Us   + NDIR*12*USP;
    float* recs = hs   + NDIR*512*HSP;
    float* brs  = recs + NDIR*384;

    int tid = threadIdx.x;
    int u0  = blockIdx.x * 4;

    const float* xp[2]  = {xpA, xpB};
    const float* Uw[2]  = {UA, UB};
    const float* brp[2] = {brA, brB};
    float*       yp[2]  = {yA, yB};
    int          rev[2] = {revA, revB};
    int         yoff[2] = {yoffA, yoffB};

    for (int idx = tid; idx < NDIR*12*512; idx += NTHR){
        int d = idx / (12*512); int r = idx % (12*512);
        int c = r >> 9; int k = r & 511;
        int col = (c >> 2)*512 + u0 + (c & 3);
        Us[(d*12 + c)*USP + k] = Uw[d][(size_t)k*G3 + col];
    }
    if (tid < NDIR*12){
        int d = tid / 12, c = tid % 12;
        int col = (c >> 2)*512 + u0 + (c & 3);
        brs[tid] = brp[d][col];
    }
    __syncthreads();

    int d_, c_, bf_;
    if (NDIR == 2){ d_ = tid/96; int r = tid%96; c_ = r >> 3; bf_ = (r & 7)*4; }
    else          { d_ = 0;      c_ = tid >> 4;  bf_ = (tid & 15)*2; }
    const int NB = (NDIR == 2) ? 4 : 2;

    for (int t = 0; t < TT; t++){
        if (t > 0){
            int ph = (t + 1) & 1;
            for (int idx = tid; idx < NDIR*4096; idx += NTHR){
                int d = idx >> 12; int r = idx & 4095;
                int b = r >> 7; int kq = (r & 127) * 4;
                float4 v = __ldcg((const float4*)&g_h[(size_t)(d*2+ph)*16384 + b*512 + kq]);
                float* hd = hs + d*(512*HSP) + b;
                hd[(kq+0)*HSP] = v.x; hd[(kq+1)*HSP] = v.y;
                hd[(kq+2)*HSP] = v.z; hd[(kq+3)*HSP] = v.w;
            }
        }
        __syncthreads();

        float acc[4] = {0.f, 0.f, 0.f, 0.f};
        if (t > 0){
            const float* wp = Us + (d_*12 + c_)*USP;
            const float* hp = hs + d_*(512*HSP) + bf_;
            #pragma unroll 4
            for (int k = 0; k < 512; k++){
                float w = wp[k];
                #pragma unroll
                for (int i = 0; i < NB; i++) acc[i] += hp[k*HSP + i] * w;
            }
        }
        #pragma unroll
        for (int i = 0; i < 4; i++)
            if (i < NB) recs[(d_*12 + c_)*32 + bf_ + i] = acc[i];
        __syncthreads();

        for (int idx = tid; idx < NDIR*128; idx += NTHR){
            int d = idx >> 7; int r = idx & 127;
            int u = r & 3;  int b = r >> 2;
            int unit = u0 + u;
            int base = d*384;
            float rz = recs[base + (0+u)*32 + b] + brs[d*12 + 0 + u];
            float rr = recs[base + (4+u)*32 + b] + brs[d*12 + 4 + u];
            float rh = recs[base + (8+u)*32 + b] + brs[d*12 + 8 + u];
            int tq = rev[d] ? (TT - 1 - t) : t;
            const float* xrow = xp[d] + (size_t)(b*TT + tq)*G3;
            float z  = sigf(xrow[unit]        + rz);
            float rg = sigf(xrow[512 + unit]  + rr);
            float hh = sigf(xrow[1024 + unit] + rg*rh);
            float hprev = (t == 0) ? 0.f : hs[d*(512*HSP) + unit*HSP + b];
            float hn = z*hprev + (1.f - z)*hh;
            if (!g_mask[b*TT + tq]) hn = hprev;
            g_h[(size_t)(d*2 + (t & 1))*16384 + b*512 + unit] = hn;
            yp[d][(size_t)(b*TT + tq)*ystride + yoff[d] + unit] = hn;
            if (write_hT && t == TT - 1)
                yp[d][(size_t)BB*TT*ystride + b*512 + unit] = hn;
        }
        __syncthreads();
        if (t < TT - 1){
            if (tid == 0){
                __threadfence();
                unsigned int cnt = atomicAdd(&bar[t], 1u) + 1u;
                while (cnt < NCTA){
                    __nanosleep(32);
                    cnt = *((volatile unsigned int*)&bar[t]);
                }
                __threadfence();
            }
            __syncthreads();
        }
    }
}

extern "C" void kernel_launch(void* const* d_in, const int* in_sizes, int n_in,
                              void* d_out, int out_size)
{
    const int*   x     = (const int*)  d_in[0];
    const float* E     = (const float*)d_in[2];
    const float* W_fw  = (const float*)d_in[3];
    const float* U_fw  = (const float*)d_in[4];
    const float* b_fw  = (const float*)d_in[5];
    const float* W_bw  = (const float*)d_in[6];
    const float* U_bw  = (const float*)d_in[7];
    const float* b_bw  = (const float*)d_in[8];
    const float* W_m0  = (const float*)d_in[9];
    const float* U_m0  = (const float*)d_in[10];
    const float* b_m0  = (const float*)d_in[11];
    const float* W_m1  = (const float*)d_in[12];
    const float* U_m1  = (const float*)d_in[13];
    const float* b_m1  = (const float*)d_in[14];
    const float* W_top = (const float*)d_in[15];
    const float* U_top = (const float*)d_in[16];
    const float* b_top = (const float*)d_in[17];
    float* out = (float*)d_out;

    const int SMEM2 = (2*12*USP + 2*512*HSP + 2*384 + 2*12) * 4;
    const int SMEM1 = (1*12*USP + 1*512*HSP + 1*384 + 1*12) * 4;
    cudaFuncSetAttribute((const void*)scan_kernel<2>,
                         cudaFuncAttributeMaxDynamicSharedMemorySize, SMEM2);
    cudaFuncSetAttribute((const void*)scan_kernel<1>,
                         cudaFuncAttributeMaxDynamicSharedMemorySize, SMEM1);

    float *e, *xp0, *xp1, *hcat, *y; unsigned int* bar;
    cudaGetSymbolAddress((void**)&e,    g_e);
    cudaGetSymbolAddress((void**)&xp0,  g_xp0);
    cudaGetSymbolAddress((void**)&xp1,  g_xp1);
    cudaGetSymbolAddress((void**)&hcat, g_hcat);
    cudaGetSymbolAddress((void**)&y,    g_y);
    cudaGetSymbolAddress((void**)&bar,  g_bar);

    int write_hT = (out_size >= BB*TT*512 + BB*512) ? 1 : 0;

    prep_kernel<<<1, 256>>>(x);
    embed_kernel<<<BB*TT, 128>>>(x, E);

    dim3 gg(G3/128, (BB*TT)/128);
    gemm_kernel<<<gg, 256>>>(e, 512, 512, W_fw, b_fw, xp0);
    gemm_kernel<<<gg, 256>>>(e, 512, 512, W_bw, b_bw, xp1);

    scan_kernel<2><<<NCTA, NTHR, SMEM2>>>(
        xp0, U_fw, b_fw + G3, hcat, 0, 0,
        xp1, U_bw, b_bw + G3, hcat, 1, 512,
        1024, bar + 0, 0);

    gemm_kernel<<<gg, 256>>>(hcat, 1024, 1024, W_m0, b_m0, xp0);
    scan_kernel<1><<<NCTA, NTHR, SMEM1>>>(
        xp0, U_m0, b_m0 + G3, y, 0, 0,
        xp0, U_m0, b_m0 + G3, y, 0, 0,
        512, bar + 132, 0);

    gemm_kernel<<<gg, 256>>>(y, 512, 512, W_m1, b_m1, xp0);
    scan_kernel<1><<<NCTA, NTHR, SMEM1>>>(
        xp0, U_m1, b_m1 + G3, y, 0, 0,
        xp0, U_m1, b_m1 + G3, y, 0, 0,
        512, bar + 264, 0);

    gemm_kernel<<<gg, 256>>>(y, 512, 512, W_top, b_top, xp0);
    scan_kernel<1><<<NCTA, NTHR, SMEM1>>>(
        xp0, U_top, b_top + G3, out, 0, 0,
        xp0, U_top, b_top + G3, out, 0, 0,
        512, bar + 396, write_hT);
}

// round 13
// speedup vs baseline: 1.0642x; 1.0642x over previous
#include <cuda_runtime.h>
#include <math.h>
#include <stdint.h>

#define BB   32
#define TT   128
#define G3   1536
#define NCTA 128
#define NTHR 192
#define HS   36      // padded stride (floats) for hs[k][b]; 36%4==0 -> float4 aligned
#define USP  516

__device__ float g_e   [BB*TT*512];
__device__ int   g_mask[BB*TT];
__device__ float g_xp0 [BB*TT*G3];
__device__ float g_xp1 [BB*TT*G3];
__device__ float g_hcat[BB*TT*1024];
__device__ float g_y   [BB*TT*512];
__device__ float g_h   [2*2*BB*512];
__device__ unsigned int g_bar[4*132];
__device__ int   g_is64;

__device__ __forceinline__ float sigf(float x){ return 1.f/(1.f + __expf(-x)); }

__device__ __forceinline__ unsigned long long pack2(float x){
    unsigned long long r;
    asm("mov.b64 %0, {%1, %1};" : "=l"(r) : "f"(x));
    return r;
}
__device__ __forceinline__ void fma2(unsigned long long& acc, unsigned long long a, unsigned long long b){
    asm("fma.rn.f32x2 %0, %1, %2, %0;" : "+l"(acc) : "l"(a), "l"(b));
}
__device__ __forceinline__ void unpack2(unsigned long long v, float& lo, float& hi){
    asm("mov.b64 {%0, %1}, %2;" : "=f"(lo), "=f"(hi) : "l"(v));
}

__global__ void prep_kernel(const int* xw){
    __shared__ int s_ok;
    if (threadIdx.x == 0) s_ok = 1;
    __syncthreads();
    int bad = 0;
    for (int i = threadIdx.x; i < 2040; i += blockDim.x)
        if (xw[2*i + 1] != 0) bad = 1;
    if (bad) atomicExch(&s_ok, 0);
    __syncthreads();
    if (threadIdx.x == 0) g_is64 = s_ok;
    for (int i = threadIdx.x; i < 4*132; i += blockDim.x) g_bar[i] = 0u;
}

__global__ void embed_kernel(const int* xw, const float* E){
    int i = blockIdx.x;
    int tok = g_is64 ? xw[2*i] : xw[i];
    if (threadIdx.x == 0) g_mask[i] = (tok != 0);
    const float4* src = (const float4*)(E + (size_t)tok * 512);
    float4* dst = (float4*)(g_e + (size_t)i * 512);
    dst[threadIdx.x] = src[threadIdx.x];
}

__global__ __launch_bounds__(256)
void gemm_kernel(const float* A, int lda, int K,
                 const float* Bm, const float* bias, float* C){
    __shared__ __align__(16) float As[8*128];
    __shared__ __align__(16) float Bs[8*128];
    int tid = threadIdx.x;
    int m0 = blockIdx.y * 128, n0 = blockIdx.x * 128;
    int tx = tid & 15, ty = tid >> 4;
    int arow = tid >> 1, akq = (tid & 1) * 4;
    int bkr  = tid >> 5, bnc = (tid & 31) * 4;
    const float* Aptr = A + (size_t)(m0 + arow) * lda + akq;
    const float* Bptr = Bm + (size_t)bkr * G3 + n0 + bnc;

    unsigned long long acc2[8][4];
    #pragma unroll
    for (int i = 0; i < 8; i++)
        #pragma unroll
        for (int j = 0; j < 4; j++) acc2[i][j] = 0ull;

    int KT = K >> 3;
    float4 ra = *(const float4*)(Aptr);
    float4 rb = *(const float4*)(Bptr);
    for (int kt = 0; kt < KT; kt++){
        As[(akq+0)*128 + arow] = ra.x;
        As[(akq+1)*128 + arow] = ra.y;
        As[(akq+2)*128 + arow] = ra.z;
        As[(akq+3)*128 + arow] = ra.w;
        *(float4*)(Bs + bkr*128 + bnc) = rb;
        __syncthreads();
        if (kt + 1 < KT){
            ra = *(const float4*)(Aptr + (kt+1)*8);
            rb = *(const float4*)(Bptr + (size_t)(kt+1)*8*G3);
        }
        #pragma unroll
        for (int kk = 0; kk < 8; kk++){
            float a[8];
            *(float4*)(a)   = *(const float4*)(As + kk*128 + ty*8);
            *(float4*)(a+4) = *(const float4*)(As + kk*128 + ty*8 + 4);
            ulonglong2 t0 = *(const ulonglong2*)(Bs + kk*128 + tx*8);
            ulonglong2 t1 = *(const ulonglong2*)(Bs + kk*128 + tx*8 + 4);
            unsigned long long b2[4] = {t0.x, t0.y, t1.x, t1.y};
            unsigned long long ap[8];
            #pragma unroll
            for (int i = 0; i < 8; i++) ap[i] = pack2(a[i]);
            #pragma unroll
            for (int i = 0; i < 8; i++)
                #pragma unroll
                for (int j = 0; j < 4; j++) fma2(acc2[i][j], ap[i], b2[j]);
        }
        __syncthreads();
    }
    float bb[8];
    #pragma unroll
    for (int j = 0; j < 8; j++) bb[j] = bias[n0 + tx*8 + j];
    #pragma unroll
    for (int i = 0; i < 8; i++){
        float c[8];
        #pragma unroll
        for (int j = 0; j < 4; j++) unpack2(acc2[i][j], c[2*j], c[2*j+1]);
        float* crow = C + (size_t)(m0 + ty*8 + i)*G3 + n0 + tx*8;
        float4 o0, o1;
        o0.x = c[0]+bb[0]; o0.y = c[1]+bb[1]; o0.z = c[2]+bb[2]; o0.w = c[3]+bb[3];
        o1.x = c[4]+bb[4]; o1.y = c[5]+bb[5]; o1.z = c[6]+bb[6]; o1.w = c[7]+bb[7];
        *(float4*)(crow)     = o0;
        *(float4*)(crow + 4) = o1;
    }
}

// 128 CTAs (1/SM), each owns 4 units. U slice in SMEM for all steps.
// NDIR=2: fw+bw fused (12 cols x 8 batch-quads x 2 dirs = 192 threads, K=512 each).
// NDIR=1: K split in half (12 x 8 x 2 halves = 192 threads, K=256 each + reduce).
template<int NDIR>
__global__ __launch_bounds__(NTHR)
void scan_kernel(const float* xpA, const float* UA, const float* brA, float* yA, int revA, int yoffA,
                 const float* xpB, const float* UB, const float* brB, float* yB, int revB, int yoffB,
                 int ystride, unsigned int* bar, int write_hT)
{
    extern __shared__ __align__(16) float sm[];
    float* Us   = sm;                            // NDIR*12*USP
    float* hs   = Us   + NDIR*12*USP;            // NDIR*512*HS  ([k][b], padded)
    float* recs = hs   + NDIR*512*HS;            // 24*32
    float* brs  = recs + 24*32;                  // NDIR*12

    const int KSPLIT = (NDIR == 1) ? 2 : 1;
    int tid = threadIdx.x;
    int u0  = blockIdx.x * 4;

    const float* xp[2]  = {xpA, xpB};
    const float* Uw[2]  = {UA, UB};
    const float* brp[2] = {brA, brB};
    float*       yp[2]  = {yA, yB};
    int          rev[2] = {revA, revB};
    int         yoff[2] = {yoffA, yoffB};

    for (int idx = tid; idx < NDIR*12*512; idx += NTHR){
        int d = idx / (12*512); int r = idx % (12*512);
        int c = r >> 9; int k = r & 511;
        int col = (c >> 2)*512 + u0 + (c & 3);
        Us[(d*12 + c)*USP + k] = Uw[d][(size_t)k*G3 + col];
    }
    if (tid < NDIR*12){
        int d = tid / 12, c = tid % 12;
        int col = (c >> 2)*512 + u0 + (c & 3);
        brs[tid] = brp[d][col];
    }
    __syncthreads();

    int d_, c_, bf_, kb_;
    if (NDIR == 2){ d_ = tid/96; int r = tid%96; c_ = r >> 3; bf_ = (r & 7)*4; kb_ = 0; }
    else          { d_ = 0; int kh = tid/96; int r = tid%96; c_ = r >> 3; bf_ = (r & 7)*4; kb_ = kh*256; }
    const int KLEN = (NDIR == 2) ? 512 : 256;
    int slot = (NDIR == 2) ? (d_*12 + c_) : (c_*2 + (kb_ >> 8));

    for (int t = 0; t < TT; t++){
        if (t > 0){
            int ph = (t + 1) & 1;
            for (int idx = tid; idx < NDIR*4096; idx += NTHR){
                int d = idx >> 12; int r = idx & 4095;
                int b = r >> 7; int kq = (r & 127) * 4;
                float4 v = __ldcg((const float4*)&g_h[(size_t)(d*2+ph)*16384 + b*512 + kq]);
                float* hd = hs + d*(512*HS) + b;
                hd[(kq+0)*HS] = v.x; hd[(kq+1)*HS] = v.y;
                hd[(kq+2)*HS] = v.z; hd[(kq+3)*HS] = v.w;
            }
        }
        __syncthreads();

        unsigned long long a01 = 0ull, a23 = 0ull;
        if (t > 0){
            const float* wp = Us + (d_*12 + c_)*USP;
            const ulonglong2* hp = (const ulonglong2*)(hs + d_*(512*HS) + bf_);
            #pragma unroll 4
            for (int k = kb_; k < kb_ + KLEN; k++){
                unsigned long long ww = pack2(wp[k]);
                ulonglong2 hv = hp[k*(HS/4)];
                fma2(a01, hv.x, ww);
                fma2(a23, hv.y, ww);
            }
        }
        {
            float f0, f1, f2, f3;
            unpack2(a01, f0, f1); unpack2(a23, f2, f3);
            *(float4*)(recs + slot*32 + bf_) = make_float4(f0, f1, f2, f3);
        }
        __syncthreads();

        for (int idx = tid; idx < NDIR*128; idx += NTHR){
            int d = idx >> 7; int r = idx & 127;
            int u = r & 3;  int b = r >> 2;
            int unit = u0 + u;
            float rz, rr, rh;
            if (NDIR == 2){
                int base = d*384;
                rz = recs[base + (0+u)*32 + b];
                rr = recs[base + (4+u)*32 + b];
                rh = recs[base + (8+u)*32 + b];
            } else {
                rz = recs[((0+u)*2)*32 + b] + recs[((0+u)*2+1)*32 + b];
                rr = recs[((4+u)*2)*32 + b] + recs[((4+u)*2+1)*32 + b];
                rh = recs[((8+u)*2)*32 + b] + recs[((8+u)*2+1)*32 + b];
            }
            rz += brs[d*12 + 0 + u];
            rr += brs[d*12 + 4 + u];
            rh += brs[d*12 + 8 + u];
            int tq = rev[d] ? (TT - 1 - t) : t;
            const float* xrow = xp[d] + (size_t)(b*TT + tq)*G3;
            float z  = sigf(xrow[unit]        + rz);
            float rg = sigf(xrow[512 + unit]  + rr);
            float hh = sigf(xrow[1024 + unit] + rg*rh);
            float hprev = (t == 0) ? 0.f : hs[d*(512*HS) + unit*HS + b];
            float hn = z*hprev + (1.f - z)*hh;
            if (!g_mask[b*TT + tq]) hn = hprev;
            g_h[(size_t)(d*2 + (t & 1))*16384 + b*512 + unit] = hn;
            yp[d][(size_t)(b*TT + tq)*ystride + yoff[d] + unit] = hn;
            if (write_hT && t == TT - 1)
                yp[d][(size_t)BB*TT*ystride + b*512 + unit] = hn;
        }
        __syncthreads();
        if (t < TT - 1){
            if (tid == 0){
                unsigned int cnt;
                asm volatile("fence.acq_rel.gpu;" ::: "memory");
                asm volatile("red.relaxed.gpu.global.add.u32 [%0], 1;" :: "l"(bar + t) : "memory");
                do {
                    asm volatile("ld.relaxed.gpu.global.u32 %0, [%1];" : "=r"(cnt) : "l"(bar + t) : "memory");
                } while (cnt < NCTA);
                asm volatile("fence.acq_rel.gpu;" ::: "memory");
            }
            __syncthreads();
        }
    }
}

extern "C" void kernel_launch(void* const* d_in, const int* in_sizes, int n_in,
                              void* d_out, int out_size)
{
    const int*   x     = (const int*)  d_in[0];
    const float* E     = (const float*)d_in[2];
    const float* W_fw  = (const float*)d_in[3];
    const float* U_fw  = (const float*)d_in[4];
    const float* b_fw  = (const float*)d_in[5];
    const float* W_bw  = (const float*)d_in[6];
    const float* U_bw  = (const float*)d_in[7];
    const float* b_bw  = (const float*)d_in[8];
    const float* W_m0  = (const float*)d_in[9];
    const float* U_m0  = (const float*)d_in[10];
    const float* b_m0  = (const float*)d_in[11];
    const float* W_m1  = (const float*)d_in[12];
    const float* U_m1  = (const float*)d_in[13];
    const float* b_m1  = (const float*)d_in[14];
    const float* W_top = (const float*)d_in[15];
    const float* U_top = (const float*)d_in[16];
    const float* b_top = (const float*)d_in[17];
    float* out = (float*)d_out;

    const int SMEM2 = (2*12*USP + 2*512*HS + 24*32 + 2*12) * 4;
    const int SMEM1 = (1*12*USP + 1*512*HS + 24*32 + 1*12) * 4;
    cudaFuncSetAttribute((const void*)scan_kernel<2>,
                         cudaFuncAttributeMaxDynamicSharedMemorySize, SMEM2);
    cudaFuncSetAttribute((const void*)scan_kernel<1>,
                         cudaFuncAttributeMaxDynamicSharedMemorySize, SMEM1);

    float *e, *xp0, *xp1, *hcat, *y; unsigned int* bar;
    cudaGetSymbolAddress((void**)&e,    g_e);
    cudaGetSymbolAddress((void**)&xp0,  g_xp0);
    cudaGetSymbolAddress((void**)&xp1,  g_xp1);
    cudaGetSymbolAddress((void**)&hcat, g_hcat);
    cudaGetSymbolAddress((void**)&y,    g_y);
    cudaGetSymbolAddress((void**)&bar,  g_bar);

    int write_hT = (out_size >= BB*TT*512 + BB*512) ? 1 : 0;

    prep_kernel<<<1, 256>>>(x);
    embed_kernel<<<BB*TT, 128>>>(x, E);

    dim3 gg(G3/128, (BB*TT)/128);
    gemm_kernel<<<gg, 256>>>(e, 512, 512, W_fw, b_fw, xp0);
    gemm_kernel<<<gg, 256>>>(e, 512, 512, W_bw, b_bw, xp1);

    scan_kernel<2><<<NCTA, NTHR, SMEM2>>>(
        xp0, U_fw, b_fw + G3, hcat, 0, 0,
        xp1, U_bw, b_bw + G3, hcat, 1, 512,
        1024, bar + 0, 0);

    gemm_kernel<<<gg, 256>>>(hcat, 1024, 1024, W_m0, b_m0, xp0);
    scan_kernel<1><<<NCTA, NTHR, SMEM1>>>(
        xp0, U_m0, b_m0 + G3, y, 0, 0,
        xp0, U_m0, b_m0 + G3, y, 0, 0,
        512, bar + 132, 0);

    gemm_kernel<<<gg, 256>>>(y, 512, 512, W_m1, b_m1, xp0);
    scan_kernel<1><<<NCTA, NTHR, SMEM1>>>(
        xp0, U_m1, b_m1 + G3, y, 0, 0,
        xp0, U_m1, b_m1 + G3, y, 0, 0,
        512, bar + 264, 0);

    gemm_kernel<<<gg, 256>>>(y, 512, 512, W_top, b_top, xp0);
    scan_kernel<1><<<NCTA, NTHR, SMEM1>>>(
        xp0, U_top, b_top + G3, out, 0, 0,
        xp0, U_top, b_top + G3, out, 0, 0,
        512, bar + 396, write_hT);
}

// round 14
// speedup vs baseline: 1.3024x; 1.2238x over previous
#include <cuda_runtime.h>
#include <math.h>
#include <stdint.h>

#define BB   32
#define TT   128
#define G3   1536
#define NCTA 128

__device__ float g_e   [BB*TT*512];
__device__ int   g_mask[BB*TT];
__device__ float g_xp0 [BB*TT*G3];
__device__ float g_xp1 [BB*TT*G3];
__device__ float g_hcat[BB*TT*1024];
__device__ float g_y   [BB*TT*512];
__device__ float g_h   [2*2*512*32];      // [dir][phase][k][b]
__device__ unsigned int g_bar[4*128];
__device__ int   g_is64;

__device__ __forceinline__ float sigf(float x){ return 1.f/(1.f + __expf(-x)); }

__global__ void prep_kernel(const int* xw){
    __shared__ int s_ok;
    if (threadIdx.x == 0) s_ok = 1;
    __syncthreads();
    int bad = 0;
    for (int i = threadIdx.x; i < 2040; i += blockDim.x)
        if (xw[2*i + 1] != 0) bad = 1;
    if (bad) atomicExch(&s_ok, 0);
    __syncthreads();
    if (threadIdx.x == 0) g_is64 = s_ok;
    for (int i = threadIdx.x; i < 4*128; i += blockDim.x) g_bar[i] = 0u;
}

__global__ void embed_kernel(const int* xw, const float* E){
    int i = blockIdx.x;
    int tok = g_is64 ? xw[2*i] : xw[i];
    if (threadIdx.x == 0) g_mask[i] = (tok != 0);
    const float4* src = (const float4*)(E + (size_t)tok * 512);
    float4* dst = (float4*)(g_e + (size_t)i * 512);
    dst[threadIdx.x] = src[threadIdx.x];
}

__global__ __launch_bounds__(256)
void gemm_kernel(const float* A, int lda, int K,
                 const float* Bm, const float* bias, float* C){
    __shared__ __align__(16) float As[8*128];
    __shared__ __align__(16) float Bs[8*128];
    int tid = threadIdx.x;
    int m0 = blockIdx.y * 128, n0 = blockIdx.x * 128;
    int tx = tid & 15, ty = tid >> 4;
    int arow = tid >> 1, akq = (tid & 1) * 4;
    int bkr  = tid >> 5, bnc = (tid & 31) * 4;
    const float* Aptr = A + (size_t)(m0 + arow) * lda + akq;
    const float* Bptr = Bm + (size_t)bkr * G3 + n0 + bnc;

    float acc[8][8];
    #pragma unroll
    for (int i = 0; i < 8; i++)
        #pragma unroll
        for (int j = 0; j < 8; j++) acc[i][j] = 0.f;

    int KT = K >> 3;
    float4 ra = *(const float4*)(Aptr);
    float4 rb = *(const float4*)(Bptr);
    for (int kt = 0; kt < KT; kt++){
        As[(akq+0)*128 + arow] = ra.x;
        As[(akq+1)*128 + arow] = ra.y;
        As[(akq+2)*128 + arow] = ra.z;
        As[(akq+3)*128 + arow] = ra.w;
        *(float4*)(Bs + bkr*128 + bnc) = rb;
        __syncthreads();
        if (kt + 1 < KT){
            ra = *(const float4*)(Aptr + (kt+1)*8);
            rb = *(const float4*)(Bptr + (size_t)(kt+1)*8*G3);
        }
        #pragma unroll
        for (int kk = 0; kk < 8; kk++){
            float a[8], b[8];
            *(float4*)(a)   = *(const float4*)(As + kk*128 + ty*8);
            *(float4*)(a+4) = *(const float4*)(As + kk*128 + ty*8 + 4);
            *(float4*)(b)   = *(const float4*)(Bs + kk*128 + tx*8);
            *(float4*)(b+4) = *(const float4*)(Bs + kk*128 + tx*8 + 4);
            #pragma unroll
            for (int i = 0; i < 8; i++)
                #pragma unroll
                for (int j = 0; j < 8; j++) acc[i][j] += a[i]*b[j];
        }
        __syncthreads();
    }
    float bb[8];
    #pragma unroll
    for (int j = 0; j < 8; j++) bb[j] = bias[n0 + tx*8 + j];
    #pragma unroll
    for (int i = 0; i < 8; i++){
        float* crow = C + (size_t)(m0 + ty*8 + i)*G3 + n0 + tx*8;
        float4 o0, o1;
        o0.x = acc[i][0]+bb[0]; o0.y = acc[i][1]+bb[1]; o0.z = acc[i][2]+bb[2]; o0.w = acc[i][3]+bb[3];
        o1.x = acc[i][4]+bb[4]; o1.y = acc[i][5]+bb[5]; o1.z = acc[i][6]+bb[6]; o1.w = acc[i][7]+bb[7];
        *(float4*)(crow)     = o0;
        *(float4*)(crow + 4) = o1;
    }
}

// Persistent scan: 128 CTAs x 256 threads. Each CTA owns 4 units (12 U-cols/dir).
// Dot phase: thread tile (3 cols x 8 batches), K split across warps, partial
// reduction via SMEM. h staged per step as a straight [k][b] copy.
template<int NDIR>
__global__ __launch_bounds__(256)
void scan_kernel(const float* xpA, const float* UA, const float* brA, float* yA, int revA, int yoffA,
                 const float* xpB, const float* UB, const float* brB, float* yB, int revB, int yoffB,
                 int ystride, unsigned int* flag, int write_hT)
{
    extern __shared__ __align__(16) float sm[];
    const int KS  = (NDIR == 2) ? 8 : 16;    // number of K chunks
    const int CH  = 512 / KS;                 // chunk length
    const int SZ  = NDIR * 12 * 33;           // ps row stride (floats)
    float* Us   = sm;                          // [NDIR][512][12]
    float* hs   = Us   + NDIR*6144;            // [NDIR][512][32]
    float* ps   = hs   + NDIR*16384;           // [KS][SZ]
    float* recs = ps   + KS*SZ;                // [NDIR*384]
    float* brs  = recs + NDIR*384;             // [NDIR][12]

    int tid  = threadIdx.x;
    int w    = tid >> 5;
    int lane = tid & 31;
    int u0   = blockIdx.x * 4;

    const float* xp[2]  = {xpA, xpB};
    const float* Uw[2]  = {UA, UB};
    const float* brp[2] = {brA, brB};
    float*       yp[2]  = {yA, yB};
    int          rev[2] = {revA, revB};
    int         yoff[2] = {yoffA, yoffB};

    // Load U slices: Us[d][k][c], c -> global col (c>>2)*512 + u0 + (c&3)
    for (int idx = tid; idx < NDIR*6144; idx += 256){
        int d = idx / 6144; int r = idx % 6144;
        int k = r / 12; int c = r % 12;
        int col = (c >> 2)*512 + u0 + (c & 3);
        Us[idx] = Uw[d][(size_t)k*G3 + col];
    }
    if (tid < NDIR*12){
        int d = tid / 12, c = tid % 12;
        brs[tid] = brp[d][(c >> 2)*512 + u0 + (c & 3)];
    }
    __syncthreads();

    // dot-phase thread mapping
    int d_, ks_, cg_, bg_;
    if (NDIR == 2){ d_ = lane >> 4; int r = lane & 15; cg_ = r >> 2; bg_ = r & 3; ks_ = w; }
    else          { d_ = 0; int ksub = lane >> 4; int r = lane & 15; cg_ = r >> 2; bg_ = r & 3; ks_ = w*2 + ksub; }
    int c0 = cg_*3, b0 = bg_*8;

    // gate-phase mapping
    int gd = tid >> 7, gr = tid & 127, gu = gr & 3, gb = gr >> 2;
    bool gact = (tid < NDIR*128);

    for (int t = 0; t < TT; t++){
        // ---- prefetch x + mask for this step's gates ----
        float px0 = 0.f, px1 = 0.f, px2 = 0.f; int pm = 0, tq_g = 0;
        if (gact){
            tq_g = rev[gd] ? (TT - 1 - t) : t;
            const float* xr = xp[gd] + (size_t)(gb*TT + tq_g)*G3 + u0 + gu;
            px0 = __ldg(xr); px1 = __ldg(xr + 512); px2 = __ldg(xr + 1024);
            pm  = g_mask[gb*TT + tq_g];
        }

        // ---- stage h (straight copy, g_h and hs share [k][b] layout) ----
        if (t > 0){
            int ph = (t + 1) & 1;
            for (int idx = tid; idx < NDIR*4096; idx += 256){
                int d = idx >> 12; int r = idx & 4095;
                float4 v = __ldcg(((const float4*)&g_h[(size_t)(d*2+ph)*16384]) + r);
                *(((float4*)&hs[d*16384]) + r) = v;
            }
        }
        __syncthreads();

        // ---- dot: rec partials ----
        if (t > 0){
            float acc[3][8];
            #pragma unroll
            for (int i = 0; i < 3; i++)
                #pragma unroll
                for (int j = 0; j < 8; j++) acc[i][j] = 0.f;
            const float* up = Us + (d_*512 + ks_*CH)*12 + c0;
            const float* hp = hs + (d_*512 + ks_*CH)*32 + b0;
            #pragma unroll 4
            for (int k = 0; k < CH; k++){
                float u0v = up[k*12 + 0];
                float u1v = up[k*12 + 1];
                float u2v = up[k*12 + 2];
                float4 h0 = *(const float4*)(hp + k*32);
                float4 h1 = *(const float4*)(hp + k*32 + 4);
                float hv[8] = {h0.x,h0.y,h0.z,h0.w,h1.x,h1.y,h1.z,h1.w};
                #pragma unroll
                for (int j = 0; j < 8; j++){
                    acc[0][j] += u0v * hv[j];
                    acc[1][j] += u1v * hv[j];
                    acc[2][j] += u2v * hv[j];
                }
            }
            float* pr = ps + ks_*SZ + (d_*12 + c0)*33 + b0;
            #pragma unroll
            for (int i = 0; i < 3; i++)
                #pragma unroll
                for (int j = 0; j < 8; j++) pr[i*33 + j] = acc[i][j];
        }
        __syncthreads();

        // ---- reduce partials -> recs ----
        for (int o = tid; o < NDIR*384; o += 256){
            int d = o / 384; int rr = o % 384;
            int c = rr >> 5; int b = rr & 31;
            int slot = (d*12 + c)*33 + b;
            float s = 0.f;
            if (t > 0){
                #pragma unroll
                for (int ks = 0; ks < KS; ks++) s += ps[ks*SZ + slot];
            }
            recs[o] = s;
        }
        __syncthreads();

        // ---- gates ----
        if (gact){
            float rz = recs[gd*384 + (0*4+gu)*32 + gb] + brs[gd*12 + 0 + gu];
            float rr = recs[gd*384 + (1*4+gu)*32 + gb] + brs[gd*12 + 4 + gu];
            float rh = recs[gd*384 + (2*4+gu)*32 + gb] + brs[gd*12 + 8 + gu];
            float z  = sigf(px0 + rz);
            float rg = sigf(px1 + rr);
            float hh = sigf(px2 + rg*rh);
            float hprev = (t == 0) ? 0.f : hs[(gd*512 + u0 + gu)*32 + gb];
            float hn = z*hprev + (1.f - z)*hh;
            if (!pm) hn = hprev;
            g_h[(size_t)(gd*2 + (t & 1))*16384 + (u0 + gu)*32 + gb] = hn;
            yp[gd][(size_t)(gb*TT + tq_g)*ystride + yoff[gd] + u0 + gu] = hn;
            if (write_hT && t == TT - 1)
                yp[gd][(size_t)BB*TT*ystride + gb*512 + u0 + gu] = hn;
        }
        __syncthreads();

        // ---- grid barrier (distributed flags) ----
        if (t < TT - 1){
            if (tid == 0){
                asm volatile("fence.acq_rel.gpu;" ::: "memory");
                asm volatile("st.relaxed.gpu.global.u32 [%0], %1;"
                             :: "l"(flag + blockIdx.x), "r"((unsigned)(t + 1)) : "memory");
            }
            if (tid < NCTA){
                unsigned v;
                do {
                    asm volatile("ld.relaxed.gpu.global.u32 %0, [%1];"
                                 : "=r"(v) : "l"(flag + tid) : "memory");
                } while (v < (unsigned)(t + 1));
            }
            __syncthreads();
        }
    }
}

extern "C" void kernel_launch(void* const* d_in, const int* in_sizes, int n_in,
                              void* d_out, int out_size)
{
    const int*   x     = (const int*)  d_in[0];
    const float* E     = (const float*)d_in[2];
    const float* W_fw  = (const float*)d_in[3];
    const float* U_fw  = (const float*)d_in[4];
    const float* b_fw  = (const float*)d_in[5];
    const float* W_bw  = (const float*)d_in[6];
    const float* U_bw  = (const float*)d_in[7];
    const float* b_bw  = (const float*)d_in[8];
    const float* W_m0  = (const float*)d_in[9];
    const float* U_m0  = (const float*)d_in[10];
    const float* b_m0  = (const float*)d_in[11];
    const float* W_m1  = (const float*)d_in[12];
    const float* U_m1  = (const float*)d_in[13];
    const float* b_m1  = (const float*)d_in[14];
    const float* W_top = (const float*)d_in[15];
    const float* U_top = (const float*)d_in[16];
    const float* b_top = (const float*)d_in[17];
    float* out = (float*)d_out;

    const int SMEM2 = (2*6144 + 2*16384 + 8*(2*12*33) + 2*384 + 2*12) * 4;
    const int SMEM1 = (1*6144 + 1*16384 + 16*(1*12*33) + 1*384 + 1*12) * 4;
    cudaFuncSetAttribute((const void*)scan_kernel<2>,
                         cudaFuncAttributeMaxDynamicSharedMemorySize, SMEM2);
    cudaFuncSetAttribute((const void*)scan_kernel<1>,
                         cudaFuncAttributeMaxDynamicSharedMemorySize, SMEM1);

    float *e, *xp0, *xp1, *hcat, *y; unsigned int* bar;
    cudaGetSymbolAddress((void**)&e,    g_e);
    cudaGetSymbolAddress((void**)&xp0,  g_xp0);
    cudaGetSymbolAddress((void**)&xp1,  g_xp1);
    cudaGetSymbolAddress((void**)&hcat, g_hcat);
    cudaGetSymbolAddress((void**)&y,    g_y);
    cudaGetSymbolAddress((void**)&bar,  g_bar);

    int write_hT = (out_size >= BB*TT*512 + BB*512) ? 1 : 0;

    prep_kernel<<<1, 256>>>(x);
    embed_kernel<<<BB*TT, 128>>>(x, E);

    dim3 gg(G3/128, (BB*TT)/128);
    gemm_kernel<<<gg, 256>>>(e, 512, 512, W_fw, b_fw, xp0);
    gemm_kernel<<<gg, 256>>>(e, 512, 512, W_bw, b_bw, xp1);

    scan_kernel<2><<<NCTA, 256, SMEM2>>>(
        xp0, U_fw, b_fw + G3, hcat, 0, 0,
        xp1, U_bw, b_bw + G3, hcat, 1, 512,
        1024, bar + 0, 0);

    gemm_kernel<<<gg, 256>>>(hcat, 1024, 1024, W_m0, b_m0, xp0);
    scan_kernel<1><<<NCTA, 256, SMEM1>>>(
        xp0, U_m0, b_m0 + G3, y, 0, 0,
        xp0, U_m0, b_m0 + G3, y, 0, 0,
        512, bar + 128, 0);

    gemm_kernel<<<gg, 256>>>(y, 512, 512, W_m1, b_m1, xp0);
    scan_kernel<1><<<NCTA, 256, SMEM1>>>(
        xp0, U_m1, b_m1 + G3, y, 0, 0,
        xp0, U_m1, b_m1 + G3, y, 0, 0,
        512, bar + 256, 0);

    gemm_kernel<<<gg, 256>>>(y, 512, 512, W_top, b_top, xp0);
    scan_kernel<1><<<NCTA, 256, SMEM1>>>(
        xp0, U_top, b_top + G3, out, 0, 0,
        xp0, U_top, b_top + G3, out, 0, 0,
        512, bar + 384, write_hT);
}

// round 15
// speedup vs baseline: 1.7808x; 1.3673x over previous
#include <cuda_runtime.h>
#include <math.h>
#include <stdint.h>

#define BB   32
#define TT   128
#define G3   1536
#define NCTA 128

__device__ float g_e   [BB*TT*512];
__device__ int   g_mask[BB*TT];
__device__ float g_xp0 [BB*TT*G3];
__device__ float g_xp1 [BB*TT*G3];
__device__ float g_hcat[BB*TT*1024];
__device__ float g_y   [BB*TT*512];
__device__ float g_h   [8*512*16];        // [sub*2+phase][k][b]  (max NB=16)
__device__ unsigned int g_bar[4*128];
__device__ int   g_is64;

__device__ __forceinline__ float sigf(float x){ return 1.f/(1.f + __expf(-x)); }

__global__ void prep_kernel(const int* xw){
    __shared__ int s_ok;
    if (threadIdx.x == 0) s_ok = 1;
    __syncthreads();
    int bad = 0;
    for (int i = threadIdx.x; i < 2040; i += blockDim.x)
        if (xw[2*i + 1] != 0) bad = 1;
    if (bad) atomicExch(&s_ok, 0);
    __syncthreads();
    if (threadIdx.x == 0) g_is64 = s_ok;
    for (int i = threadIdx.x; i < 4*128; i += blockDim.x) g_bar[i] = 0u;
}

__global__ void embed_kernel(const int* xw, const float* E){
    int i = blockIdx.x;
    int tok = g_is64 ? xw[2*i] : xw[i];
    if (threadIdx.x == 0) g_mask[i] = (tok != 0);
    const float4* src = (const float4*)(E + (size_t)tok * 512);
    float4* dst = (float4*)(g_e + (size_t)i * 512);
    dst[threadIdx.x] = src[threadIdx.x];
}

__global__ __launch_bounds__(256)
void gemm_kernel(const float* A, int lda, int K,
                 const float* Bm, const float* bias, float* C){
    __shared__ __align__(16) float As[8*128];
    __shared__ __align__(16) float Bs[8*128];
    int tid = threadIdx.x;
    int m0 = blockIdx.y * 128, n0 = blockIdx.x * 128;
    int tx = tid & 15, ty = tid >> 4;
    int arow = tid >> 1, akq = (tid & 1) * 4;
    int bkr  = tid >> 5, bnc = (tid & 31) * 4;
    const float* Aptr = A + (size_t)(m0 + arow) * lda + akq;
    const float* Bptr = Bm + (size_t)bkr * G3 + n0 + bnc;

    float acc[8][8];
    #pragma unroll
    for (int i = 0; i < 8; i++)
        #pragma unroll
        for (int j = 0; j < 8; j++) acc[i][j] = 0.f;

    int KT = K >> 3;
    float4 ra = *(const float4*)(Aptr);
    float4 rb = *(const float4*)(Bptr);
    for (int kt = 0; kt < KT; kt++){
        As[(akq+0)*128 + arow] = ra.x;
        As[(akq+1)*128 + arow] = ra.y;
        As[(akq+2)*128 + arow] = ra.z;
        As[(akq+3)*128 + arow] = ra.w;
        *(float4*)(Bs + bkr*128 + bnc) = rb;
        __syncthreads();
        if (kt + 1 < KT){
            ra = *(const float4*)(Aptr + (kt+1)*8);
            rb = *(const float4*)(Bptr + (size_t)(kt+1)*8*G3);
        }
        #pragma unroll
        for (int kk = 0; kk < 8; kk++){
            float a[8], b[8];
            *(float4*)(a)   = *(const float4*)(As + kk*128 + ty*8);
            *(float4*)(a+4) = *(const float4*)(As + kk*128 + ty*8 + 4);
            *(float4*)(b)   = *(const float4*)(Bs + kk*128 + tx*8);
            *(float4*)(b+4) = *(const float4*)(Bs + kk*128 + tx*8 + 4);
            #pragma unroll
            for (int i = 0; i < 8; i++)
                #pragma unroll
                for (int j = 0; j < 8; j++) acc[i][j] += a[i]*b[j];
        }
        __syncthreads();
    }
    float bb[8];
    #pragma unroll
    for (int j = 0; j < 8; j++) bb[j] = bias[n0 + tx*8 + j];
    #pragma unroll
    for (int i = 0; i < 8; i++){
        float* crow = C + (size_t)(m0 + ty*8 + i)*G3 + n0 + tx*8;
        float4 o0, o1;
        o0.x = acc[i][0]+bb[0]; o0.y = acc[i][1]+bb[1]; o0.z = acc[i][2]+bb[2]; o0.w = acc[i][3]+bb[3];
        o1.x = acc[i][4]+bb[4]; o1.y = acc[i][5]+bb[5]; o1.z = acc[i][6]+bb[6]; o1.w = acc[i][7]+bb[7];
        *(float4*)(crow)     = o0;
        *(float4*)(crow + 4) = o1;
    }
}

// 2-D persistent scan: 128 CTAs = 32 unit-groups (16 units) x 4 subgroups.
// BIDI=1: subgroups = {dir}x{2 batch halves of 16}. BIDI=0: 4 batch quarters of 8.
// Each subgroup of 32 CTAs syncs only among itself (distributed flags).
template<int BIDI>
__global__ __launch_bounds__(256)
void scan_kernel(const float* xpF, const float* UF, const float* brF, float* yF, int yoffF,
                 const float* xpB, const float* UB, const float* brB, float* yB, int yoffB,
                 int ystride, unsigned int* flag, int write_hT)
{
    constexpr int NB  = BIDI ? 16 : 8;     // batches per CTA
    constexpr int HB  = NB / 2;            // batches per dot-thread
    constexpr int NBP = NB + 1;            // padded stride
    extern __shared__ __align__(16) float sm[];
    float* Us   = sm;                      // [512][48]
    float* hs   = Us   + 512*48;           // [512][NB]
    float* ps   = hs   + 512*NB;           // [8][48*NBP]
    float* recs = ps   + 8*48*NBP;         // [48*NBP]
    float* brs  = recs + 48*NBP;           // [48]

    int tid = threadIdx.x;
    int bid = blockIdx.x;
    int sub = bid >> 5;                          // 0..3
    int dir = BIDI ? (sub >> 1) : 0;
    int bg0 = BIDI ? ((sub & 1) * 16) : (sub * 8);
    int u0  = (bid & 31) * 16;
    int rev = BIDI ? dir : 0;

    const float* xp = dir ? xpB : xpF;
    const float* Uw = dir ? UB  : UF;
    const float* br = dir ? brB : brF;
    float*       yp = dir ? yB  : yF;
    int        yoff = dir ? yoffB : yoffF;

    for (int idx = tid; idx < 512*48; idx += 256){
        int k = idx / 48, c = idx % 48;
        int col = (c >> 4)*512 + u0 + (c & 15);
        Us[idx] = Uw[(size_t)k*G3 + col];
    }
    if (tid < 48) brs[tid] = br[(tid >> 4)*512 + u0 + (tid & 15)];
    __syncthreads();

    int ks   = tid >> 5;
    int lane = tid & 31;
    int c0   = (lane >> 1) * 3;
    int b0   = (lane & 1) * HB;

    int gu  = tid & 15, gbr = tid >> 4;
    bool gact = (tid < 16*NB);

    for (int t = 0; t < TT; t++){
        float px0 = 0.f, px1 = 0.f, px2 = 0.f; int pm = 0, tq = 0, gb = 0;
        if (gact){
            tq = rev ? (TT - 1 - t) : t;
            gb = bg0 + gbr;
            const float* xr = xp + (size_t)(gb*TT + tq)*G3 + u0 + gu;
            px0 = __ldg(xr); px1 = __ldg(xr + 512); px2 = __ldg(xr + 1024);
            pm  = g_mask[gb*TT + tq];
        }

        if (t > 0){
            int ph = (t + 1) & 1;
            const float4* src = (const float4*)&g_h[(size_t)(sub*2 + ph)*512*NB];
            float4* dst = (float4*)hs;
            #pragma unroll
            for (int r = tid; r < 128*NB; r += 256) dst[r] = __ldcg(src + r);
        }
        __syncthreads();

        float acc[3][HB];
        #pragma unroll
        for (int i = 0; i < 3; i++)
            #pragma unroll
            for (int j = 0; j < HB; j++) acc[i][j] = 0.f;
        if (t > 0){
            const float*  up  = Us + ks*(64*48) + c0;
            const float4* hp4 = (const float4*)(hs + ks*64*NB + b0);
            #pragma unroll 4
            for (int k = 0; k < 64; k++){
                float uv0 = up[k*48], uv1 = up[k*48 + 1], uv2 = up[k*48 + 2];
                float hv[HB];
                *(float4*)hv = hp4[k*(NB/4)];
                if (HB == 8) *(float4*)(hv + 4) = hp4[k*(NB/4) + 1];
                #pragma unroll
                for (int j = 0; j < HB; j++){
                    acc[0][j] += uv0 * hv[j];
                    acc[1][j] += uv1 * hv[j];
                    acc[2][j] += uv2 * hv[j];
                }
            }
        }
        {
            float* pr = ps + ks*(48*NBP) + c0*NBP + b0;
            #pragma unroll
            for (int i = 0; i < 3; i++)
                #pragma unroll
                for (int j = 0; j < HB; j++) pr[i*NBP + j] = acc[i][j];
        }
        __syncthreads();

        for (int o = tid; o < 48*NB; o += 256){
            int c = o / NB, b = o % NB;
            int slot = c*NBP + b;
            float s = 0.f;
            if (t > 0){
                #pragma unroll
                for (int q = 0; q < 8; q++) s += ps[q*(48*NBP) + slot];
            }
            recs[slot] = s;
        }
        __syncthreads();

        if (gact){
            float rz = recs[(0  + gu)*NBP + gbr] + brs[gu];
            float rr = recs[(16 + gu)*NBP + gbr] + brs[16 + gu];
            float rh = recs[(32 + gu)*NBP + gbr] + brs[32 + gu];
            float z  = sigf(px0 + rz);
            float rg = sigf(px1 + rr);
            float hh = sigf(px2 + rg*rh);
            float hprev = (t == 0) ? 0.f : hs[(u0 + gu)*NB + gbr];
            float hn = z*hprev + (1.f - z)*hh;
            if (!pm) hn = hprev;
            g_h[(size_t)(sub*2 + (t & 1))*512*NB + (u0 + gu)*NB + gbr] = hn;
            yp[(size_t)(gb*TT + tq)*ystride + yoff + u0 + gu] = hn;
            if (write_hT && t == TT - 1)
                yp[(size_t)BB*TT*ystride + gb*512 + u0 + gu] = hn;
        }
        __syncthreads();

        if (t < TT - 1){
            if (tid == 0){
                asm volatile("fence.acq_rel.gpu;" ::: "memory");
                asm volatile("st.relaxed.gpu.global.u32 [%0], %1;"
                             :: "l"(flag + (sub*32) + (bid & 31)), "r"((unsigned)(t + 1)) : "memory");
            }
            if (tid < 32){
                unsigned v;
                do {
                    asm volatile("ld.relaxed.gpu.global.u32 %0, [%1];"
                                 : "=r"(v) : "l"(flag + (sub*32) + tid) : "memory");
                } while (v < (unsigned)(t + 1));
                asm volatile("fence.acq_rel.gpu;" ::: "memory");
            }
            __syncthreads();
        }
    }
}

extern "C" void kernel_launch(void* const* d_in, const int* in_sizes, int n_in,
                              void* d_out, int out_size)
{
    const int*   x     = (const int*)  d_in[0];
    const float* E     = (const float*)d_in[2];
    const float* W_fw  = (const float*)d_in[3];
    const float* U_fw  = (const float*)d_in[4];
    const float* b_fw  = (const float*)d_in[5];
    const float* W_bw  = (const float*)d_in[6];
    const float* U_bw  = (const float*)d_in[7];
    const float* b_bw  = (const float*)d_in[8];
    const float* W_m0  = (const float*)d_in[9];
    const float* U_m0  = (const float*)d_in[10];
    const float* b_m0  = (const float*)d_in[11];
    const float* W_m1  = (const float*)d_in[12];
    const float* U_m1  = (const float*)d_in[13];
    const float* b_m1  = (const float*)d_in[14];
    const float* W_top = (const float*)d_in[15];
    const float* U_top = (const float*)d_in[16];
    const float* b_top = (const float*)d_in[17];
    float* out = (float*)d_out;

    const int SMEM2 = (512*48 + 512*16 + 8*48*17 + 48*17 + 48) * 4;
    const int SMEM1 = (512*48 + 512*8  + 8*48*9  + 48*9  + 48) * 4;
    cudaFuncSetAttribute((const void*)scan_kernel<1>,
                         cudaFuncAttributeMaxDynamicSharedMemorySize, SMEM2);
    cudaFuncSetAttribute((const void*)scan_kernel<0>,
                         cudaFuncAttributeMaxDynamicSharedMemorySize, SMEM1);

    float *e, *xp0, *xp1, *hcat, *y; unsigned int* bar;
    cudaGetSymbolAddress((void**)&e,    g_e);
    cudaGetSymbolAddress((void**)&xp0,  g_xp0);
    cudaGetSymbolAddress((void**)&xp1,  g_xp1);
    cudaGetSymbolAddress((void**)&hcat, g_hcat);
    cudaGetSymbolAddress((void**)&y,    g_y);
    cudaGetSymbolAddress((void**)&bar,  g_bar);

    int write_hT = (out_size >= BB*TT*512 + BB*512) ? 1 : 0;

    prep_kernel<<<1, 256>>>(x);
    embed_kernel<<<BB*TT, 128>>>(x, E);

    dim3 gg(G3/128, (BB*TT)/128);
    gemm_kernel<<<gg, 256>>>(e, 512, 512, W_fw, b_fw, xp0);
    gemm_kernel<<<gg, 256>>>(e, 512, 512, W_bw, b_bw, xp1);

    scan_kernel<1><<<NCTA, 256, SMEM2>>>(
        xp0, U_fw, b_fw + G3, hcat, 0,
        xp1, U_bw, b_bw + G3, hcat, 512,
        1024, bar + 0, 0);

    gemm_kernel<<<gg, 256>>>(hcat, 1024, 1024, W_m0, b_m0, xp0);
    scan_kernel<0><<<NCTA, 256, SMEM1>>>(
        xp0, U_m0, b_m0 + G3, y, 0,
        xp0, U_m0, b_m0 + G3, y, 0,
        512, bar + 128, 0);

    gemm_kernel<<<gg, 256>>>(y, 512, 512, W_m1, b_m1, xp0);
    scan_kernel<0><<<NCTA, 256, SMEM1>>>(
        xp0, U_m1, b_m1 + G3, y, 0,
        xp0, U_m1, b_m1 + G3, y, 0,
        512, bar + 256, 0);

    gemm_kernel<<<gg, 256>>>(y, 512, 512, W_top, b_top, xp0);
    scan_kernel<0><<<NCTA, 256, SMEM1>>>(
        xp0, U_top, b_top + G3, out, 0,
        xp0, U_top, b_top + G3, out, 0,
        512, bar + 384, write_hT);
}

// round 16
// speedup vs baseline: 1.8648x; 1.0471x over previous
#include <cuda_runtime.h>
#include <math.h>
#include <stdint.h>

#define BB   32
#define TT   128
#define G3   1536
#define NCTA 128

__device__ float g_e   [BB*TT*512];
__device__ int   g_mask[BB*TT];
__device__ float g_xp0 [BB*TT*G3];
__device__ float g_xp1 [BB*TT*G3];
__device__ float g_hcat[BB*TT*1024];
__device__ float g_y   [BB*TT*512];
__device__ float g_h   [8*512*16];        // [sub*2+phase][k][b]  (max NB=16)
__device__ unsigned int g_bar[4*128];
__device__ int   g_is64;

__device__ __forceinline__ float sigf(float x){ return 1.f/(1.f + __expf(-x)); }

__global__ void prep_kernel(const int* xw){
    __shared__ int s_ok;
    if (threadIdx.x == 0) s_ok = 1;
    __syncthreads();
    int bad = 0;
    for (int i = threadIdx.x; i < 2040; i += blockDim.x)
        if (xw[2*i + 1] != 0) bad = 1;
    if (bad) atomicExch(&s_ok, 0);
    __syncthreads();
    if (threadIdx.x == 0) g_is64 = s_ok;
    for (int i = threadIdx.x; i < 4*128; i += blockDim.x) g_bar[i] = 0u;
}

__global__ void embed_kernel(const int* xw, const float* E){
    int i = blockIdx.x;
    int tok = g_is64 ? xw[2*i] : xw[i];
    if (threadIdx.x == 0) g_mask[i] = (tok != 0);
    const float4* src = (const float4*)(E + (size_t)tok * 512);
    float4* dst = (float4*)(g_e + (size_t)i * 512);
    dst[threadIdx.x] = src[threadIdx.x];
}

__global__ __launch_bounds__(256)
void gemm_kernel(const float* A, int lda, int K,
                 const float* Bm, const float* bias, float* C){
    __shared__ __align__(16) float As[8*128];
    __shared__ __align__(16) float Bs[8*128];
    int tid = threadIdx.x;
    int m0 = blockIdx.y * 128, n0 = blockIdx.x * 128;
    int tx = tid & 15, ty = tid >> 4;
    int arow = tid >> 1, akq = (tid & 1) * 4;
    int bkr  = tid >> 5, bnc = (tid & 31) * 4;
    const float* Aptr = A + (size_t)(m0 + arow) * lda + akq;
    const float* Bptr = Bm + (size_t)bkr * G3 + n0 + bnc;

    float acc[8][8];
    #pragma unroll
    for (int i = 0; i < 8; i++)
        #pragma unroll
        for (int j = 0; j < 8; j++) acc[i][j] = 0.f;

    int KT = K >> 3;
    float4 ra = *(const float4*)(Aptr);
    float4 rb = *(const float4*)(Bptr);
    for (int kt = 0; kt < KT; kt++){
        As[(akq+0)*128 + arow] = ra.x;
        As[(akq+1)*128 + arow] = ra.y;
        As[(akq+2)*128 + arow] = ra.z;
        As[(akq+3)*128 + arow] = ra.w;
        *(float4*)(Bs + bkr*128 + bnc) = rb;
        __syncthreads();
        if (kt + 1 < KT){
            ra = *(const float4*)(Aptr + (kt+1)*8);
            rb = *(const float4*)(Bptr + (size_t)(kt+1)*8*G3);
        }
        #pragma unroll
        for (int kk = 0; kk < 8; kk++){
            float a[8], b[8];
            *(float4*)(a)   = *(const float4*)(As + kk*128 + ty*8);
            *(float4*)(a+4) = *(const float4*)(As + kk*128 + ty*8 + 4);
            *(float4*)(b)   = *(const float4*)(Bs + kk*128 + tx*8);
            *(float4*)(b+4) = *(const float4*)(Bs + kk*128 + tx*8 + 4);
            #pragma unroll
            for (int i = 0; i < 8; i++)
                #pragma unroll
                for (int j = 0; j < 8; j++) acc[i][j] += a[i]*b[j];
        }
        __syncthreads();
    }
    float bb[8];
    #pragma unroll
    for (int j = 0; j < 8; j++) bb[j] = bias[n0 + tx*8 + j];
    #pragma unroll
    for (int i = 0; i < 8; i++){
        float* crow = C + (size_t)(m0 + ty*8 + i)*G3 + n0 + tx*8;
        float4 o0, o1;
        o0.x = acc[i][0]+bb[0]; o0.y = acc[i][1]+bb[1]; o0.z = acc[i][2]+bb[2]; o0.w = acc[i][3]+bb[3];
        o1.x = acc[i][4]+bb[4]; o1.y = acc[i][5]+bb[5]; o1.z = acc[i][6]+bb[6]; o1.w = acc[i][7]+bb[7];
        *(float4*)(crow)     = o0;
        *(float4*)(crow + 4) = o1;
    }
}

// 2-D persistent scan: 128 CTAs = 32 unit-groups (16 units) x 4 subgroups.
// BIDI=1: subgroups = {dir}x{2 batch halves of 16}. BIDI=0: 4 batch quarters of 8.
// Gate threads fuse the 8-way K-partial reduction; per-subgroup flag barrier.
template<int BIDI>
__global__ __launch_bounds__(256)
void scan_kernel(const float* xpF, const float* UF, const float* brF, float* yF, int yoffF,
                 const float* xpB, const float* UB, const float* brB, float* yB, int yoffB,
                 int ystride, unsigned int* flag, int write_hT)
{
    constexpr int NB  = BIDI ? 16 : 8;
    constexpr int HB  = NB / 2;
    constexpr int NBP = NB + 1;
    extern __shared__ __align__(16) float sm[];
    float* Us  = sm;                       // [512][48]
    float* hs  = Us + 512*48;              // [512][NB]
    float* ps  = hs + 512*NB;              // [8][48*NBP]
    float* brs = ps + 8*48*NBP;            // [48]

    int tid = threadIdx.x;
    int bid = blockIdx.x;
    int sub = bid >> 5;
    int dir = BIDI ? (sub >> 1) : 0;
    int bg0 = BIDI ? ((sub & 1) * 16) : (sub * 8);
    int u0  = (bid & 31) * 16;
    int rev = BIDI ? dir : 0;

    const float* xp = dir ? xpB : xpF;
    const float* Uw = dir ? UB  : UF;
    const float* br = dir ? brB : brF;
    float*       yp = dir ? yB  : yF;
    int        yoff = dir ? yoffB : yoffF;

    for (int idx = tid; idx < 512*48; idx += 256){
        int k = idx / 48, c = idx % 48;
        int col = (c >> 4)*512 + u0 + (c & 15);
        Us[idx] = Uw[(size_t)k*G3 + col];
    }
    if (tid < 48) brs[tid] = br[(tid >> 4)*512 + u0 + (tid & 15)];
    __syncthreads();

    int ks   = tid >> 5;
    int lane = tid & 31;
    int c0   = (lane >> 1) * 3;
    int b0   = (lane & 1) * HB;

    int gu  = tid & 15, gbr = tid >> 4;
    bool gact = (tid < 16*NB);

    // bias preload (registers)
    float bz = 0.f, brr = 0.f, bh = 0.f;
    if (gact){ bz = brs[gu]; brr = brs[16 + gu]; bh = brs[32 + gu]; }

    for (int t = 0; t < TT; t++){
        float px0 = 0.f, px1 = 0.f, px2 = 0.f; int pm = 0, tq = 0, gb = 0;
        if (gact){
            tq = rev ? (TT - 1 - t) : t;
            gb = bg0 + gbr;
            const float* xr = xp + (size_t)(gb*TT + tq)*G3 + u0 + gu;
            px0 = __ldg(xr); px1 = __ldg(xr + 512); px2 = __ldg(xr + 1024);
            pm  = g_mask[gb*TT + tq];
        }

        if (t > 0){
            int ph = (t + 1) & 1;
            const float4* src = (const float4*)&g_h[(size_t)(sub*2 + ph)*512*NB];
            float4* dst = (float4*)hs;
            for (int r = tid; r < 128*NB; r += 256) dst[r] = __ldcg(src + r);
        }
        __syncthreads();

        if (t > 0){
            float acc[3][HB];
            #pragma unroll
            for (int i = 0; i < 3; i++)
                #pragma unroll
                for (int j = 0; j < HB; j++) acc[i][j] = 0.f;
            const float*  up  = Us + ks*(64*48) + c0;
            const float4* hp4 = (const float4*)(hs + ks*64*NB + b0);
            #pragma unroll 4
            for (int k = 0; k < 64; k++){
                float uv0 = up[k*48], uv1 = up[k*48 + 1], uv2 = up[k*48 + 2];
                float hv[HB];
                *(float4*)hv = hp4[k*(NB/4)];
                if (HB == 8) *(float4*)(hv + 4) = hp4[k*(NB/4) + 1];
                #pragma unroll
                for (int j = 0; j < HB; j++){
                    acc[0][j] += uv0 * hv[j];
                    acc[1][j] += uv1 * hv[j];
                    acc[2][j] += uv2 * hv[j];
                }
            }
            float* pr = ps + ks*(48*NBP) + c0*NBP + b0;
            #pragma unroll
            for (int i = 0; i < 3; i++)
                #pragma unroll
                for (int j = 0; j < HB; j++) pr[i*NBP + j] = acc[i][j];
        }
        __syncthreads();

        if (gact){
            float rz = bz, rr = brr, rh = bh;
            if (t > 0){
                #pragma unroll
                for (int q = 0; q < 8; q++){
                    const float* pq = ps + q*(48*NBP);
                    rz += pq[(0  + gu)*NBP + gbr];
                    rr += pq[(16 + gu)*NBP + gbr];
                    rh += pq[(32 + gu)*NBP + gbr];
                }
            }
            float z  = sigf(px0 + rz);
            float rg = sigf(px1 + rr);
            float hh = sigf(px2 + rg*rh);
            float hprev = (t == 0) ? 0.f : hs[(u0 + gu)*NB + gbr];
            float hn = z*hprev + (1.f - z)*hh;
            if (!pm) hn = hprev;
            g_h[(size_t)(sub*2 + (t & 1))*512*NB + (u0 + gu)*NB + gbr] = hn;
            yp[(size_t)(gb*TT + tq)*ystride + yoff + u0 + gu] = hn;
            if (write_hT && t == TT - 1)
                yp[(size_t)BB*TT*ystride + gb*512 + u0 + gu] = hn;
        }
        __syncthreads();

        if (t < TT - 1){
            if (tid == 0){
                asm volatile("fence.acq_rel.gpu;" ::: "memory");
                asm volatile("st.relaxed.gpu.global.u32 [%0], %1;"
                             :: "l"(flag + (sub*32) + (bid & 31)), "r"((unsigned)(t + 1)) : "memory");
            }
            if (tid < 32){
                unsigned v;
                do {
                    asm volatile("ld.acquire.gpu.global.u32 %0, [%1];"
                                 : "=r"(v) : "l"(flag + (sub*32) + tid) : "memory");
                } while (v < (unsigned)(t + 1));
            }
            __syncthreads();
        }
    }
}

extern "C" void kernel_launch(void* const* d_in, const int* in_sizes, int n_in,
                              void* d_out, int out_size)
{
    const int*   x     = (const int*)  d_in[0];
    const float* E     = (const float*)d_in[2];
    const float* W_fw  = (const float*)d_in[3];
    const float* U_fw  = (const float*)d_in[4];
    const float* b_fw  = (const float*)d_in[5];
    const float* W_bw  = (const float*)d_in[6];
    const float* U_bw  = (const float*)d_in[7];
    const float* b_bw  = (const float*)d_in[8];
    const float* W_m0  = (const float*)d_in[9];
    const float* U_m0  = (const float*)d_in[10];
    const float* b_m0  = (const float*)d_in[11];
    const float* W_m1  = (const float*)d_in[12];
    const float* U_m1  = (const float*)d_in[13];
    const float* b_m1  = (const float*)d_in[14];
    const float* W_top = (const float*)d_in[15];
    const float* U_top = (const float*)d_in[16];
    const float* b_top = (const float*)d_in[17];
    float* out = (float*)d_out;

    const int SMEM2 = (512*48 + 512*16 + 8*48*17 + 48) * 4;
    const int SMEM1 = (512*48 + 512*8  + 8*48*9  + 48) * 4;
    cudaFuncSetAttribute((const void*)scan_kernel<1>,
                         cudaFuncAttributeMaxDynamicSharedMemorySize, SMEM2);
    cudaFuncSetAttribute((const void*)scan_kernel<0>,
                         cudaFuncAttributeMaxDynamicSharedMemorySize, SMEM1);

    float *e, *xp0, *xp1, *hcat, *y; unsigned int* bar;
    cudaGetSymbolAddress((void**)&e,    g_e);
    cudaGetSymbolAddress((void**)&xp0,  g_xp0);
    cudaGetSymbolAddress((void**)&xp1,  g_xp1);
    cudaGetSymbolAddress((void**)&hcat, g_hcat);
    cudaGetSymbolAddress((void**)&y,    g_y);
    cudaGetSymbolAddress((void**)&bar,  g_bar);

    int write_hT = (out_size >= BB*TT*512 + BB*512) ? 1 : 0;

    prep_kernel<<<1, 256>>>(x);
    embed_kernel<<<BB*TT, 128>>>(x, E);

    dim3 gg(G3/128, (BB*TT)/128);
    gemm_kernel<<<gg, 256>>>(e, 512, 512, W_fw, b_fw, xp0);
    gemm_kernel<<<gg, 256>>>(e, 512, 512, W_bw, b_bw, xp1);

    scan_kernel<1><<<NCTA, 256, SMEM2>>>(
        xp0, U_fw, b_fw + G3, hcat, 0,
        xp1, U_bw, b_bw + G3, hcat, 512,
        1024, bar + 0, 0);

    gemm_kernel<<<gg, 256>>>(hcat, 1024, 1024, W_m0, b_m0, xp0);
    scan_kernel<0><<<NCTA, 256, SMEM1>>>(
        xp0, U_m0, b_m0 + G3, y, 0,
        xp0, U_m0, b_m0 + G3, y, 0,
        512, bar + 128, 0);

    gemm_kernel<<<gg, 256>>>(y, 512, 512, W_m1, b_m1, xp0);
    scan_kernel<0><<<NCTA, 256, SMEM1>>>(
        xp0, U_m1, b_m1 + G3, y, 0,
        xp0, U_m1, b_m1 + G3, y, 0,
        512, bar + 256, 0);

    gemm_kernel<<<gg, 256>>>(y, 512, 512, W_top, b_top, xp0);
    scan_kernel<0><<<NCTA, 256, SMEM1>>>(
        xp0, U_top, b_top + G3, out, 0,
        xp0, U_top, b_top + G3, out, 0,
        512, bar + 384, write_hT);
}